// round 12
// baseline (speedup 1.0000x reference)
#include <cuda_runtime.h>

// NaturalCubicSplinePotential — GB300 sm_103a
//
// R11: packed f32x2 index math. The per-element prefix chain (t5 = x*s+o,
// tm = t5+MAGIC, f_i = tm-MAGIC, v = t5-f_i) is element-independent, so it is
// computed 2 elements/instruction via PTX fma.rn.f32x2 / add.rn.f32x2 (SASS
// FFMA2 — unreachable from C++, PTX-only per the sm_103a quickref). Rounding
// is identical to the scalar .rn versions -> bit-identical result.
// Instructions/elem ~9.5 -> ~7.5.
//
// Verified-kept (R10 WIN base): grid 888 = 148x6 exact single wave with
// same-marginal double-chunk assignment; conflict-free float4/NSLOT=8 slotted
// gather; TABN=224 (PADL=48, |x|<=7); closed-form [1,4,1] inverse (31-tap
// conv); magic floor + midpoint recentering; fused deterministic reduction.

#define NM 8
#define NN 128
#define TABN 224
#define PADL 48
#define NSLOT 8
#define EVAL_BLOCKS 888
#define F4_PER_CHUNK 4096          // 16384 elements per chunk
#define NTHREADS 256
#define CONV_R 15

__device__ float g_part[EVAL_BLOCKS];
__device__ unsigned int g_ticket;   // zero-init; self-resets each call

#define LOG2_LAM 1.89996863f        // log2(2+sqrt(3))
#define INV_D0   1.07735027f        // 1/(1-lam^-2)
#define MAGIC_I  0x4B400000

#define PK2(c) (((unsigned long long)(c)) | (((unsigned long long)(c)) << 32))

// ---------------------------------------------------------------------------
// Packed 2-element index derivation + scalar gather/Horner.
// t5 = x*15.875 + 111.0 ; tm = t5 + MAGIC ; f_i = tm - MAGIC (exact float i);
// v = t5 - f_i in [-0.5, 0.5) ; i = bits(tm) - MAGIC_I.
__device__ __forceinline__ void eval_pair(float xlo, float xhi,
                                          const float4* __restrict__ tslot,
                                          float& accL, float& accH)
{
    const unsigned long long SC2  = PK2(0x417E0000u);  //  15.875f
    const unsigned long long OF2  = PK2(0x42DE0000u);  //  111.0f
    const unsigned long long MG2  = PK2(0x4B400000u);  //  12582912.0f
    const unsigned long long NMG2 = PK2(0xCB400000u);  // -12582912.0f
    const unsigned long long NON2 = PK2(0xBF800000u);  // -1.0f

    unsigned long long x2, t2, tm2, fi2, v2;
    asm("mov.b64 %0, {%1, %2};" : "=l"(x2) : "f"(xlo), "f"(xhi));
    asm("fma.rn.f32x2 %0, %1, %2, %3;" : "=l"(t2)  : "l"(x2),  "l"(SC2),  "l"(OF2));
    asm("add.rn.f32x2 %0, %1, %2;"     : "=l"(tm2) : "l"(t2),  "l"(MG2));
    asm("add.rn.f32x2 %0, %1, %2;"     : "=l"(fi2) : "l"(tm2), "l"(NMG2));
    asm("fma.rn.f32x2 %0, %1, %2, %3;" : "=l"(v2)  : "l"(fi2), "l"(NON2), "l"(t2));

    unsigned int bl, bh;
    asm("mov.b64 {%0, %1}, %2;" : "=r"(bl), "=r"(bh) : "l"(tm2));
    float vl, vh;
    asm("mov.b64 {%0, %1}, %2;" : "=f"(vl), "=f"(vh) : "l"(v2));

    const float4 cfl = tslot[((int)bl - MAGIC_I) * NSLOT];
    const float4 cfh = tslot[((int)bh - MAGIC_I) * NSLOT];
    accL += __fmaf_rn(vl, __fmaf_rn(vl, __fmaf_rn(vl, cfl.w, cfl.z), cfl.y), cfl.x);
    accH += __fmaf_rn(vh, __fmaf_rn(vh, __fmaf_rn(vh, cfh.w, cfh.z), cfh.y), cfh.x);
}

__device__ __forceinline__ void eval_chunk(const float4* __restrict__ x4, int chunk,
                                           int tid, const float4* __restrict__ tslot,
                                           float& a0, float& a1, float& a2, float& a3)
{
    const float4* p = x4 + (size_t)chunk * F4_PER_CHUNK + tid;
#pragma unroll 4
    for (int it = 0; it < F4_PER_CHUNK / NTHREADS; ++it) {
        const float4 v = p[it * NTHREADS];
        eval_pair(v.x, v.y, tslot, a0, a1);
        eval_pair(v.z, v.w, tslot, a2, a3);
    }
}

__global__ void __launch_bounds__(NTHREADS, 6)
eval_kernel(const float4* __restrict__ x4,
            const float* __restrict__ nodal,
            float* __restrict__ out)
{
    __shared__ float4 tab[TABN * NSLOT];                // 28 KB, lane-slotted
    __shared__ float  ysh[NN];
    __shared__ float  pw[256];                          // pw[k] = lam^{-k}
    __shared__ float  srsh[NN + 2 * (CONV_R + 1)];      // padded (-1)^j * r_j
    __shared__ float  csh[NN];
    __shared__ float  wsum[NTHREADS / 32];
    __shared__ bool   amLast;

    const int tid = threadIdx.x;
    const int b   = blockIdx.x;

    // second chunk (same marginal as chunk b, or -1)
    int chunk1 = -1;
    if (b >= 504 && b < 512)      chunk1 = b + 384;   // 888..895
    else if (b >= 768 && b < 888) chunk1 = b + 128;   // 896..1015
    else if (b >= 760 && b < 768) chunk1 = b + 256;   // 1016..1023

    // marginal: 4 chunks per (bs,f) slab; marginal = (chunk>>2) & 7
    const int m = (b >> 2) & 7;

    // ---- prologue: closed-form spline solve --------------------------------
    if (tid < NN)
        ysh[tid] = nodal[m * NN + tid];
    pw[tid] = exp2f(-LOG2_LAM * (float)tid);
    if (tid < NN + 2 * (CONV_R + 1))
        srsh[tid] = 0.0f;
    __syncthreads();

    const float inv_h2 = (127.0f / 8.0f) * (127.0f / 8.0f);
    if (tid >= 1 && tid <= 126) {
        float r = 3.0f * (ysh[tid - 1] - 2.0f * ysh[tid] + ysh[tid + 1]) * inv_h2;
        srsh[(CONV_R + 1) + tid] = (tid & 1) ? -r : r;
    }
    __syncthreads();

    if (tid < NN) {
        const int i = tid;
        float c = 0.0f;
        if (i >= 1 && i <= 126) {
#pragma unroll
            for (int dj = -CONV_R; dj <= CONV_R; ++dj) {
                const int j  = i + dj;
                const int jc = min(max(j, 1), 126);
                const int mi = min(i, jc);
                const int mx = max(i, jc);
                const float w = pw[(dj < 0 ? -dj : dj) + 1]
                              * (1.0f - pw[2 * mi])
                              * (1.0f - pw[2 * (127 - mx)]);
                c = __fmaf_rn(w, srsh[(CONV_R + 1) + j], c);
            }
            c *= INV_D0;
            if (i & 1) c = -c;
        }
        csh[i] = c;
    }
    __syncthreads();

    // ---- padded + midpoint-recentered table, 8 slots -----------------------
    if (tid < TABN) {
        const float h  = 8.0f / 127.0f;
        const float h2 = h * h;
        const int j  = tid;
        const int it = j - PADL;
        const int k  = min(max(it, 0), 126);
        const float s = (float)(it - k) + 0.5f;     // shift incl. midpoint

        const float A  = ysh[k];
        const float c0 = csh[k];
        const float c1 = csh[k + 1];
        const float B  = (ysh[k + 1] - A) - h2 * (2.0f * c0 + c1) * (1.0f / 3.0f);
        const float C  = c0 * h2;
        const float D  = (c1 - c0) * h2 * (1.0f / 3.0f);

        const float4 cf = make_float4(A + s * (B + s * (C + s * D)),
                                      B + s * (2.0f * C + 3.0f * D * s),
                                      C + 3.0f * D * s,
                                      D);
#pragma unroll
        for (int sl = 0; sl < NSLOT; ++sl)
            tab[j * NSLOT + sl] = cf;
    }
    __syncthreads();

    // ---- main evaluation: 1 or 2 same-marginal chunks ----------------------
    const float4* tslot = tab + (tid & 7);          // this lane's bank-quad

    float a0 = 0.0f, a1 = 0.0f, a2 = 0.0f, a3 = 0.0f;
    eval_chunk(x4, b, tid, tslot, a0, a1, a2, a3);
    if (chunk1 >= 0)
        eval_chunk(x4, chunk1, tid, tslot, a0, a1, a2, a3);

    float s = (a0 + a1) + (a2 + a3);
#pragma unroll
    for (int o = 16; o > 0; o >>= 1)
        s += __shfl_xor_sync(0xFFFFFFFFu, s, o);

    if ((tid & 31) == 0)
        wsum[tid >> 5] = s;
    __syncthreads();

    if (tid == 0) {
        float t = 0.0f;
#pragma unroll
        for (int w = 0; w < NTHREADS / 32; ++w)
            t += wsum[w];
        g_part[b] = t;
        __threadfence();
        const unsigned int ticket = atomicAdd(&g_ticket, 1u);
        amLast = (ticket == EVAL_BLOCKS - 1);
    }
    __syncthreads();

    // ---- last block: deterministic fixed-order final reduction -------------
    if (amLast) {
        __threadfence();
        float r = 0.0f;
#pragma unroll
        for (int i = 0; i < 4; ++i) {
            const int idx = tid + i * NTHREADS;
            if (idx < EVAL_BLOCKS)
                r += g_part[idx];
        }

        __shared__ float sh[NTHREADS];
        sh[tid] = r;
        __syncthreads();
#pragma unroll
        for (int st = NTHREADS / 2; st > 0; st >>= 1) {
            if (tid < st)
                sh[tid] += sh[tid + st];
            __syncthreads();
        }
        if (tid == 0) {
            out[0] = sh[0];
            g_ticket = 0u;   // reset for next call / graph replay
        }
    }
}

// ---------------------------------------------------------------------------
extern "C" void kernel_launch(void* const* d_in, const int* in_sizes, int n_in,
                              void* d_out, int out_size)
{
    const float* x     = (const float*)d_in[0];        // (32,8,256,256) fp32
    const float* nodal = (const float*)d_in[1];        // (8,128) fp32
    float* out = (float*)d_out;

    eval_kernel<<<EVAL_BLOCKS, NTHREADS>>>((const float4*)x, nodal, out);
}

// round 13
// speedup vs baseline: 1.0105x; 1.0105x over previous
#include <cuda_runtime.h>

// NaturalCubicSplinePotential — GB300 sm_103a
//
// R12: revert R11's packed-f32x2 experiment (issue dropped but the fused
// pair-chain serialized the index derivation -> latency-bound kernel got
// slower). Base = R10 winner (25.4us). Single low-risk change: fully unroll
// the 16-iter chunk loop so ptxas can front-batch LDG.128 to the 40-reg
// budget (deeper MLP) and hoist gathers across Horner chains.
//
// Verified-kept: grid 888 = 148x6 exact single wave with same-marginal
// double-chunk assignment; conflict-free float4/NSLOT=8 slotted gather
// (measured L1 floor ~15.8us); TABN=224 (PADL=48, covers |x|<=7);
// closed-form [1,4,1] inverse (31-tap conv); magic floor + midpoint
// recentering; fused deterministic last-block reduction.

#define NM 8
#define NN 128
#define TABN 224
#define PADL 48
#define NSLOT 8
#define EVAL_BLOCKS 888
#define F4_PER_CHUNK 4096          // 16384 elements per chunk
#define NTHREADS 256
#define CONV_R 15

__device__ float g_part[EVAL_BLOCKS];
__device__ unsigned int g_ticket;   // zero-init; self-resets each call

#define LOG2_LAM 1.89996863f        // log2(2+sqrt(3))
#define INV_D0   1.07735027f        // 1/(1-lam^-2)
#define MAGIC    12582912.0f        // 1.5 * 2^23
#define MAGIC_I  0x4B400000

// ---------------------------------------------------------------------------
__device__ __forceinline__ void eval_lane(float xv, const float4* __restrict__ tslot,
                                          float& acc)
{
    // t = (x+4)*15.875 + 48 (pad), midpoint-shifted: t5 = x*15.875 + 111.0
    const float t5 = __fmaf_rn(xv, 15.875f, 111.0f);
    const float tm = t5 + MAGIC;                    // round(t5) == floor(t) a.e.
    const int   i  = __float_as_int(tm) - MAGIC_I;
    const float v  = t5 - (tm - MAGIC);             // v = u - 0.5 in [-0.5,0.5)
    const float4 cf = tslot[i * NSLOT];             // conflict-free slot gather
    acc += __fmaf_rn(v, __fmaf_rn(v, __fmaf_rn(v, cf.w, cf.z), cf.y), cf.x);
}

__device__ __forceinline__ void eval_chunk(const float4* __restrict__ x4, int chunk,
                                           int tid, const float4* __restrict__ tslot,
                                           float& a0, float& a1, float& a2, float& a3)
{
    const float4* p = x4 + (size_t)chunk * F4_PER_CHUNK + tid;
#pragma unroll
    for (int it = 0; it < F4_PER_CHUNK / NTHREADS; ++it) {   // fully unrolled (16)
        const float4 v = p[it * NTHREADS];
        eval_lane(v.x, tslot, a0);
        eval_lane(v.y, tslot, a1);
        eval_lane(v.z, tslot, a2);
        eval_lane(v.w, tslot, a3);
    }
}

__global__ void __launch_bounds__(NTHREADS, 6)
eval_kernel(const float4* __restrict__ x4,
            const float* __restrict__ nodal,
            float* __restrict__ out)
{
    __shared__ float4 tab[TABN * NSLOT];                // 28 KB, lane-slotted
    __shared__ float  ysh[NN];
    __shared__ float  pw[256];                          // pw[k] = lam^{-k}
    __shared__ float  srsh[NN + 2 * (CONV_R + 1)];      // padded (-1)^j * r_j
    __shared__ float  csh[NN];
    __shared__ float  wsum[NTHREADS / 32];
    __shared__ bool   amLast;

    const int tid = threadIdx.x;
    const int b   = blockIdx.x;

    // second chunk (same marginal as chunk b, or -1)
    int chunk1 = -1;
    if (b >= 504 && b < 512)      chunk1 = b + 384;   // 888..895
    else if (b >= 768 && b < 888) chunk1 = b + 128;   // 896..1015
    else if (b >= 760 && b < 768) chunk1 = b + 256;   // 1016..1023

    // marginal: 4 chunks per (bs,f) slab; marginal = (chunk>>2) & 7
    const int m = (b >> 2) & 7;

    // ---- prologue: closed-form spline solve --------------------------------
    if (tid < NN)
        ysh[tid] = nodal[m * NN + tid];
    pw[tid] = exp2f(-LOG2_LAM * (float)tid);
    if (tid < NN + 2 * (CONV_R + 1))
        srsh[tid] = 0.0f;
    __syncthreads();

    const float inv_h2 = (127.0f / 8.0f) * (127.0f / 8.0f);
    if (tid >= 1 && tid <= 126) {
        float r = 3.0f * (ysh[tid - 1] - 2.0f * ysh[tid] + ysh[tid + 1]) * inv_h2;
        srsh[(CONV_R + 1) + tid] = (tid & 1) ? -r : r;
    }
    __syncthreads();

    if (tid < NN) {
        const int i = tid;
        float c = 0.0f;
        if (i >= 1 && i <= 126) {
#pragma unroll
            for (int dj = -CONV_R; dj <= CONV_R; ++dj) {
                const int j  = i + dj;
                const int jc = min(max(j, 1), 126);
                const int mi = min(i, jc);
                const int mx = max(i, jc);
                const float w = pw[(dj < 0 ? -dj : dj) + 1]
                              * (1.0f - pw[2 * mi])
                              * (1.0f - pw[2 * (127 - mx)]);
                c = __fmaf_rn(w, srsh[(CONV_R + 1) + j], c);
            }
            c *= INV_D0;
            if (i & 1) c = -c;
        }
        csh[i] = c;
    }
    __syncthreads();

    // ---- padded + midpoint-recentered table, 8 slots -----------------------
    if (tid < TABN) {
        const float h  = 8.0f / 127.0f;
        const float h2 = h * h;
        const int j  = tid;
        const int it = j - PADL;
        const int k  = min(max(it, 0), 126);
        const float s = (float)(it - k) + 0.5f;     // shift incl. midpoint

        const float A  = ysh[k];
        const float c0 = csh[k];
        const float c1 = csh[k + 1];
        const float B  = (ysh[k + 1] - A) - h2 * (2.0f * c0 + c1) * (1.0f / 3.0f);
        const float C  = c0 * h2;
        const float D  = (c1 - c0) * h2 * (1.0f / 3.0f);

        const float4 cf = make_float4(A + s * (B + s * (C + s * D)),
                                      B + s * (2.0f * C + 3.0f * D * s),
                                      C + 3.0f * D * s,
                                      D);
#pragma unroll
        for (int sl = 0; sl < NSLOT; ++sl)
            tab[j * NSLOT + sl] = cf;
    }
    __syncthreads();

    // ---- main evaluation: 1 or 2 same-marginal chunks ----------------------
    const float4* tslot = tab + (tid & 7);          // this lane's bank-quad

    float a0 = 0.0f, a1 = 0.0f, a2 = 0.0f, a3 = 0.0f;
    eval_chunk(x4, b, tid, tslot, a0, a1, a2, a3);
    if (chunk1 >= 0)
        eval_chunk(x4, chunk1, tid, tslot, a0, a1, a2, a3);

    float s = (a0 + a1) + (a2 + a3);
#pragma unroll
    for (int o = 16; o > 0; o >>= 1)
        s += __shfl_xor_sync(0xFFFFFFFFu, s, o);

    if ((tid & 31) == 0)
        wsum[tid >> 5] = s;
    __syncthreads();

    if (tid == 0) {
        float t = 0.0f;
#pragma unroll
        for (int w = 0; w < NTHREADS / 32; ++w)
            t += wsum[w];
        g_part[b] = t;
        __threadfence();
        const unsigned int ticket = atomicAdd(&g_ticket, 1u);
        amLast = (ticket == EVAL_BLOCKS - 1);
    }
    __syncthreads();

    // ---- last block: deterministic fixed-order final reduction -------------
    if (amLast) {
        __threadfence();
        float r = 0.0f;
#pragma unroll
        for (int i = 0; i < 4; ++i) {
            const int idx = tid + i * NTHREADS;
            if (idx < EVAL_BLOCKS)
                r += g_part[idx];
        }

        __shared__ float sh[NTHREADS];
        sh[tid] = r;
        __syncthreads();
#pragma unroll
        for (int st = NTHREADS / 2; st > 0; st >>= 1) {
            if (tid < st)
                sh[tid] += sh[tid + st];
            __syncthreads();
        }
        if (tid == 0) {
            out[0] = sh[0];
            g_ticket = 0u;   // reset for next call / graph replay
        }
    }
}

// ---------------------------------------------------------------------------
extern "C" void kernel_launch(void* const* d_in, const int* in_sizes, int n_in,
                              void* d_out, int out_size)
{
    const float* x     = (const float*)d_in[0];        // (32,8,256,256) fp32
    const float* nodal = (const float*)d_in[1];        // (8,128) fp32
    float* out = (float*)d_out;

    eval_kernel<<<EVAL_BLOCKS, NTHREADS>>>((const float4*)x, nodal, out);
}

// round 14
// speedup vs baseline: 1.0909x; 1.0795x over previous
#include <cuda_runtime.h>

// NaturalCubicSplinePotential — GB300 sm_103a
//
// R13: perfectly balanced partition (kills R10's double-chunk straggler tail).
// grid = 888 = 148x6 exact single wave = 8 marginals x 111 blocks. Each
// marginal owns 524288 float4 (32 slabs of 16384, slab stride 131072 float4);
// block q of a marginal evaluates float4 range [ floor(q*S/111),
// floor((q+1)*S/111) )  -> 4723/4724 per block (0.02% spread), so all 6 CTAs
// of an SM finish together: no 1-CTA low-occupancy tail (R10's occ leak).
// Address decode per iter: slab = j>>14, off = j&16383 (3 ALU ops, headroom).
//
// Verified-kept: conflict-free float4/NSLOT=8 slotted gather (measured L1
// floor ~15.8us); TABN=224 (PADL=48, |x|<=7); closed-form [1,4,1] inverse
// (31-tap conv); magic floor + midpoint recentering; unroll-4 loop body
// (R11/R12 proved ptxas schedules it best); fused deterministic reduction.

#define NM 8
#define NN 128
#define TABN 224
#define PADL 48
#define NSLOT 8
#define EVAL_BLOCKS 888
#define BLOCKS_PER_M 111
#define F4_PER_M 524288            // float4 per marginal (32 slabs x 16384)
#define NTHREADS 256
#define CONV_R 15

__device__ float g_part[EVAL_BLOCKS];
__device__ unsigned int g_ticket;   // zero-init; self-resets each call

#define LOG2_LAM 1.89996863f        // log2(2+sqrt(3))
#define INV_D0   1.07735027f        // 1/(1-lam^-2)
#define MAGIC    12582912.0f        // 1.5 * 2^23
#define MAGIC_I  0x4B400000

// ---------------------------------------------------------------------------
__device__ __forceinline__ void eval_lane(float xv, const float4* __restrict__ tslot,
                                          float& acc)
{
    // t = (x+4)*15.875 + 48 (pad), midpoint-shifted: t5 = x*15.875 + 111.0
    const float t5 = __fmaf_rn(xv, 15.875f, 111.0f);
    const float tm = t5 + MAGIC;                    // round(t5) == floor(t) a.e.
    const int   i  = __float_as_int(tm) - MAGIC_I;
    const float v  = t5 - (tm - MAGIC);             // v = u - 0.5 in [-0.5,0.5)
    const float4 cf = tslot[i * NSLOT];             // conflict-free slot gather
    acc += __fmaf_rn(v, __fmaf_rn(v, __fmaf_rn(v, cf.w, cf.z), cf.y), cf.x);
}

__global__ void __launch_bounds__(NTHREADS, 6)
eval_kernel(const float4* __restrict__ x4,
            const float* __restrict__ nodal,
            float* __restrict__ out)
{
    __shared__ float4 tab[TABN * NSLOT];                // 28 KB, lane-slotted
    __shared__ float  ysh[NN];
    __shared__ float  pw[256];                          // pw[k] = lam^{-k}
    __shared__ float  srsh[NN + 2 * (CONV_R + 1)];      // padded (-1)^j * r_j
    __shared__ float  csh[NN];
    __shared__ float  wsum[NTHREADS / 32];
    __shared__ bool   amLast;

    const int tid = threadIdx.x;
    const int b   = blockIdx.x;
    const int m   = b / BLOCKS_PER_M;                   // marginal 0..7
    const int q   = b - m * BLOCKS_PER_M;               // 0..110

    // balanced float4 range of this marginal
    const int jstart = (int)(((unsigned long long)q       * F4_PER_M) / BLOCKS_PER_M);
    const int jend   = (int)(((unsigned long long)(q + 1) * F4_PER_M) / BLOCKS_PER_M);

    // ---- prologue: closed-form spline solve --------------------------------
    if (tid < NN)
        ysh[tid] = nodal[m * NN + tid];
    pw[tid] = exp2f(-LOG2_LAM * (float)tid);
    if (tid < NN + 2 * (CONV_R + 1))
        srsh[tid] = 0.0f;
    __syncthreads();

    const float inv_h2 = (127.0f / 8.0f) * (127.0f / 8.0f);
    if (tid >= 1 && tid <= 126) {
        float r = 3.0f * (ysh[tid - 1] - 2.0f * ysh[tid] + ysh[tid + 1]) * inv_h2;
        srsh[(CONV_R + 1) + tid] = (tid & 1) ? -r : r;
    }
    __syncthreads();

    if (tid < NN) {
        const int i = tid;
        float c = 0.0f;
        if (i >= 1 && i <= 126) {
#pragma unroll
            for (int dj = -CONV_R; dj <= CONV_R; ++dj) {
                const int j  = i + dj;
                const int jc = min(max(j, 1), 126);
                const int mi = min(i, jc);
                const int mx = max(i, jc);
                const float w = pw[(dj < 0 ? -dj : dj) + 1]
                              * (1.0f - pw[2 * mi])
                              * (1.0f - pw[2 * (127 - mx)]);
                c = __fmaf_rn(w, srsh[(CONV_R + 1) + j], c);
            }
            c *= INV_D0;
            if (i & 1) c = -c;
        }
        csh[i] = c;
    }
    __syncthreads();

    // ---- padded + midpoint-recentered table, 8 slots -----------------------
    if (tid < TABN) {
        const float h  = 8.0f / 127.0f;
        const float h2 = h * h;
        const int j  = tid;
        const int it = j - PADL;
        const int k  = min(max(it, 0), 126);
        const float s = (float)(it - k) + 0.5f;     // shift incl. midpoint

        const float A  = ysh[k];
        const float c0 = csh[k];
        const float c1 = csh[k + 1];
        const float B  = (ysh[k + 1] - A) - h2 * (2.0f * c0 + c1) * (1.0f / 3.0f);
        const float C  = c0 * h2;
        const float D  = (c1 - c0) * h2 * (1.0f / 3.0f);

        const float4 cf = make_float4(A + s * (B + s * (C + s * D)),
                                      B + s * (2.0f * C + 3.0f * D * s),
                                      C + 3.0f * D * s,
                                      D);
#pragma unroll
        for (int sl = 0; sl < NSLOT; ++sl)
            tab[j * NSLOT + sl] = cf;
    }
    __syncthreads();

    // ---- main evaluation: balanced range of this marginal ------------------
    // marginal-linear float4 index j -> global float4 index:
    //   slab = j >> 14, off = j & 16383, g = slab*131072 + m*16384 + off
    const float4* tslot  = tab + (tid & 7);         // this lane's bank-quad
    const int     base_m = m << 14;

    float a0 = 0.0f, a1 = 0.0f, a2 = 0.0f, a3 = 0.0f;
#pragma unroll 4
    for (int j = jstart + tid; j < jend; j += NTHREADS) {
        const int slab = j >> 14;
        const int off  = j & 16383;
        const float4 v = x4[((size_t)slab << 17) + base_m + off];
        eval_lane(v.x, tslot, a0);
        eval_lane(v.y, tslot, a1);
        eval_lane(v.z, tslot, a2);
        eval_lane(v.w, tslot, a3);
    }

    float s = (a0 + a1) + (a2 + a3);
#pragma unroll
    for (int o = 16; o > 0; o >>= 1)
        s += __shfl_xor_sync(0xFFFFFFFFu, s, o);

    if ((tid & 31) == 0)
        wsum[tid >> 5] = s;
    __syncthreads();

    if (tid == 0) {
        float t = 0.0f;
#pragma unroll
        for (int w = 0; w < NTHREADS / 32; ++w)
            t += wsum[w];
        g_part[b] = t;
        __threadfence();
        const unsigned int ticket = atomicAdd(&g_ticket, 1u);
        amLast = (ticket == EVAL_BLOCKS - 1);
    }
    __syncthreads();

    // ---- last block: deterministic fixed-order final reduction -------------
    if (amLast) {
        __threadfence();
        float r = 0.0f;
#pragma unroll
        for (int i = 0; i < 4; ++i) {
            const int idx = tid + i * NTHREADS;
            if (idx < EVAL_BLOCKS)
                r += g_part[idx];
        }

        __shared__ float sh[NTHREADS];
        sh[tid] = r;
        __syncthreads();
#pragma unroll
        for (int st = NTHREADS / 2; st > 0; st >>= 1) {
            if (tid < st)
                sh[tid] += sh[tid + st];
            __syncthreads();
        }
        if (tid == 0) {
            out[0] = sh[0];
            g_ticket = 0u;   // reset for next call / graph replay
        }
    }
}

// ---------------------------------------------------------------------------
extern "C" void kernel_launch(void* const* d_in, const int* in_sizes, int n_in,
                              void* d_out, int out_size)
{
    const float* x     = (const float*)d_in[0];        // (32,8,256,256) fp32
    const float* nodal = (const float*)d_in[1];        // (8,128) fp32
    float* out = (float*)d_out;

    eval_kernel<<<EVAL_BLOCKS, NTHREADS>>>((const float4*)x, nodal, out);
}